// round 1
// baseline (speedup 1.0000x reference)
#include <cuda_runtime.h>
#include <cstdint>

// Problem constants (from reference)
#define F 8
#define B 4096
#define V 100000
#define D 128
#define NVALS 81920

// One warp per (feature, bag). Lane l owns output floats [4l, 4l+4).
// Table rows are 512B; a warp's float4 loads cover the row fully coalesced.
__global__ __launch_bounds__(256, 8)
void ebc_pooled_kernel(const int* __restrict__ values,    // [F, NVALS]
                       const int* __restrict__ offsets,   // [F, B+1]
                       const float* __restrict__ tables,  // [F, V, D]
                       float* __restrict__ out)           // [B, F*D]
{
    const int gwarp = (blockIdx.x * blockDim.x + threadIdx.x) >> 5;
    const int lane  = threadIdx.x & 31;
    if (gwarp >= F * B) return;

    // f-major: consecutive warps share a table -> ~1-2 tables live in L2 per wave
    const int f = gwarp / B;
    const int b = gwarp - f * B;

    const int start = __ldg(offsets + f * (B + 1) + b);
    const int end   = __ldg(offsets + f * (B + 1) + b + 1);

    const int*    vals = values + (size_t)f * NVALS;
    const float4* tab  = reinterpret_cast<const float4*>(tables + (size_t)f * V * D);
    // row stride in float4 units
    const int RS4 = D / 4;  // 32

    float4 acc = make_float4(0.f, 0.f, 0.f, 0.f);

    int i = start;
    // 4x unroll: 4 independent float4 loads in flight per lane (MLP=4)
    for (; i + 4 <= end; i += 4) {
        const int i0 = __ldg(vals + i + 0);
        const int i1 = __ldg(vals + i + 1);
        const int i2 = __ldg(vals + i + 2);
        const int i3 = __ldg(vals + i + 3);
        const float4 v0 = __ldg(tab + (size_t)i0 * RS4 + lane);
        const float4 v1 = __ldg(tab + (size_t)i1 * RS4 + lane);
        const float4 v2 = __ldg(tab + (size_t)i2 * RS4 + lane);
        const float4 v3 = __ldg(tab + (size_t)i3 * RS4 + lane);
        acc.x += v0.x + v1.x + v2.x + v3.x;
        acc.y += v0.y + v1.y + v2.y + v3.y;
        acc.z += v0.z + v1.z + v2.z + v3.z;
        acc.w += v0.w + v1.w + v2.w + v3.w;
    }
    for (; i < end; ++i) {
        const int idx = __ldg(vals + i);
        const float4 v = __ldg(tab + (size_t)idx * RS4 + lane);
        acc.x += v.x; acc.y += v.y; acc.z += v.z; acc.w += v.w;
    }

    // out[b, f*D + lane*4 .. +4)
    float4* out4 = reinterpret_cast<float4*>(out);
    out4[(size_t)b * (F * D / 4) + f * RS4 + lane] = acc;
}

extern "C" void kernel_launch(void* const* d_in, const int* in_sizes, int n_in,
                              void* d_out, int out_size)
{
    const int*   values  = (const int*)d_in[0];   // [F, NVALS] int32
    const int*   offsets = (const int*)d_in[1];   // [F, B+1] int32
    const float* tables  = (const float*)d_in[2]; // [F, V, D] float32
    float*       out     = (float*)d_out;         // [B, F*D] float32

    const int total_warps = F * B;                 // 32768
    const int threads = 256;                       // 8 warps/block
    const int blocks = (total_warps * 32 + threads - 1) / threads;  // 4096

    ebc_pooled_kernel<<<blocks, threads>>>(values, offsets, tables, out);
}